// round 8
// baseline (speedup 1.0000x reference)
#include <cuda_runtime.h>

// ============================================================================
// TabNet DecisionStep, fused single-kernel implementation.
// One CTA per ghost-batch chunk of 128 rows (512 CTAs total).
// All GEMMs via packed fp32x2 FFMA (fma.rn.f32x2), activations in smem.
// Sparsemax computed in closed form (monotonicity of the reference's
// ascending-sort condition => kz = K-1 iff 1 + 255*max - sum > 0).
// ============================================================================

#define N_TOT  65536
#define DDIM   256
#define NAD    64
#define HDIM   128
#define VBS    128
#define NCHUNK 512
#define EPS_F  1e-5f
#define GAMMA_F 1.5f

// shared memory layout (in floats)
#define SM_IN    0                        // 128 x 256 activation buffer
#define SM_HB    (SM_IN + VBS*DDIM)       // 128 x 128 h buffer
#define SM_WT    (SM_HB + VBS*HDIM)       // 16 x 260 weight tile (transposed)
#define SM_PART  (SM_WT + 16*260)         // 8 x 256 column-stat partials
#define SM_TAU   (SM_PART + 8*256)        // 128 per-row sparsemax taus
#define SM_NFLOAT (SM_TAU + VBS)
#define SMEM_BYTES (SM_NFLOAT * 4)        // 221,952 B (< 227 KB)

typedef unsigned long long u64;

__device__ __forceinline__ u64 pk2(float x, float y){
  u64 r; asm("mov.b64 %0, {%1, %2};" : "=l"(r) : "f"(x), "f"(y)); return r;
}
__device__ __forceinline__ void upk2(u64 v, float &x, float &y){
  asm("mov.b64 {%0, %1}, %2;" : "=f"(x), "=f"(y) : "l"(v));
}
__device__ __forceinline__ void ffma2(u64 &d, u64 a, u64 b){
  asm("fma.rn.f32x2 %0, %1, %2, %0;" : "+l"(d) : "l"(a), "l"(b));
}
__device__ __forceinline__ float sigmf(float x){
  return 1.0f / (1.0f + __expf(-x));
}

// GEMM (128 rows x 256 cols, reduction K) + bias + ghost batch norm.
// src: smem activation matrix [128][SSTR] (uses cols 0..K-1).
// W: global [256][K] row-major (out-feature major). Result returned
// normalized in v[32][4]: thread (rg,cg) owns rows rg*32..+31, cols cg*4..+3.
template<int K, int SSTR>
__device__ __forceinline__ void gemm_gbn(
    float* smem, const float* src,
    const float* __restrict__ W, const float* __restrict__ bias,
    const float* __restrict__ gw, const float* __restrict__ gb,
    float (&v)[32][4])
{
  const int tid = threadIdx.x;
  const int rg = tid >> 6, cg = tid & 63;
  const int r0 = rg * 32, c0 = cg * 4;
  float* WT   = smem + SM_WT;
  float* PART = smem + SM_PART;

  u64 acc[32][2];
  {
    float4 bv = *(const float4*)(bias + c0);
    u64 b0 = pk2(bv.x, bv.y), b1 = pk2(bv.z, bv.w);
    #pragma unroll
    for (int i = 0; i < 32; i++){ acc[i][0] = b0; acc[i][1] = b1; }
  }

  #pragma unroll 1
  for (int kt = 0; kt < K/16; kt++){
    __syncthreads();
    {
      // stage W tile transposed: WT[kk][c] = W[c][kt*16+kk]
      const float4* wr = (const float4*)(W + (size_t)tid * K + kt*16);
      float4 q0 = wr[0], q1 = wr[1], q2 = wr[2], q3 = wr[3];
      float wl[16] = {q0.x,q0.y,q0.z,q0.w, q1.x,q1.y,q1.z,q1.w,
                      q2.x,q2.y,q2.z,q2.w, q3.x,q3.y,q3.z,q3.w};
      #pragma unroll
      for (int kk = 0; kk < 16; kk++) WT[kk*260 + tid] = wl[kk];
    }
    __syncthreads();
    const float* s0 = src + r0 * SSTR + kt*16;
    #pragma unroll
    for (int kk = 0; kk < 16; kk += 2){
      float4 wv0 = *(const float4*)(WT + kk*260 + c0);
      float4 wv1 = *(const float4*)(WT + (kk+1)*260 + c0);
      u64 w00 = pk2(wv0.x, wv0.y), w01 = pk2(wv0.z, wv0.w);
      u64 w10 = pk2(wv1.x, wv1.y), w11 = pk2(wv1.z, wv1.w);
      #pragma unroll
      for (int i = 0; i < 32; i++){
        float2 xv = *(const float2*)(s0 + i*SSTR + kk);  // warp-broadcast
        u64 x0 = pk2(xv.x, xv.x);
        u64 x1 = pk2(xv.y, xv.y);
        ffma2(acc[i][0], x0, w00);
        ffma2(acc[i][1], x0, w01);
        ffma2(acc[i][0], x1, w10);
        ffma2(acc[i][1], x1, w11);
      }
    }
  }

  // unpack + per-column (feature) partial stats over this thread's 32 rows
  float s[4] = {0,0,0,0}, q[4] = {0,0,0,0};
  #pragma unroll
  for (int i = 0; i < 32; i++){
    upk2(acc[i][0], v[i][0], v[i][1]);
    upk2(acc[i][1], v[i][2], v[i][3]);
    #pragma unroll
    for (int j = 0; j < 4; j++){ s[j] += v[i][j]; q[j] += v[i][j]*v[i][j]; }
  }
  #pragma unroll
  for (int j = 0; j < 4; j++){
    PART[rg*256 + c0 + j]        = s[j];
    PART[1024 + rg*256 + c0 + j] = q[j];
  }
  __syncthreads();
  {
    const int c = tid;   // 256 threads <-> 256 columns
    float sum = PART[c] + PART[256+c] + PART[512+c] + PART[768+c];
    float sq  = PART[1024+c] + PART[1280+c] + PART[1536+c] + PART[1792+c];
    float mean = sum * (1.0f / VBS);
    float var  = sq  * (1.0f / VBS) - mean*mean;
    float A = rsqrtf(var + EPS_F) * gw[c];
    float B = gb[c] - mean * A;
    PART[c]        = A;   // safe: only thread c reads column-c partials
    PART[1024 + c] = B;
  }
  __syncthreads();
  {
    float4 Av = *(const float4*)(PART + c0);
    float4 Bv = *(const float4*)(PART + 1024 + c0);
    #pragma unroll
    for (int i = 0; i < 32; i++){
      v[i][0] = v[i][0]*Av.x + Bv.x;
      v[i][1] = v[i][1]*Av.y + Bv.y;
      v[i][2] = v[i][2]*Av.z + Bv.z;
      v[i][3] = v[i][3]*Av.w + Bv.w;
    }
  }
}

__global__ void __launch_bounds__(256, 1)
tabnet_kernel(
  const float* __restrict__ x, const float* __restrict__ a,
  const float* __restrict__ prior,
  const float* __restrict__ w_att, const float* __restrict__ b_att,
  const float* __restrict__ gwa,  const float* __restrict__ gba,
  const float* __restrict__ w_s1, const float* __restrict__ b_s1,
  const float* __restrict__ gw1,  const float* __restrict__ gb1,
  const float* __restrict__ w_s2, const float* __restrict__ b_s2,
  const float* __restrict__ gw2,  const float* __restrict__ gb2,
  const float* __restrict__ w_d1, const float* __restrict__ b_d1,
  const float* __restrict__ gw3,  const float* __restrict__ gb3,
  const float* __restrict__ w_d2, const float* __restrict__ b_d2,
  const float* __restrict__ gw4,  const float* __restrict__ gb4,
  float* __restrict__ out)
{
  extern __shared__ float smem[];
  const int tid = threadIdx.x;
  const int chunk = blockIdx.x;
  const int rg = tid >> 6, cg = tid & 63;
  const int r0 = rg * 32, c0 = cg * 4;
  float* IN  = smem + SM_IN;
  float* HB  = smem + SM_HB;
  float* TAU = smem + SM_TAU;
  const size_t rowbase = (size_t)chunk * VBS;

  // ---- stage the `a` chunk (128 x 64) into IN ----
  {
    const float* aC = a + rowbase * NAD;
    for (int idx = tid; idx < VBS * (NAD/4); idx += 256){
      int r = idx >> 4, c4 = (idx & 15) << 2;
      *(float4*)(IN + r*DDIM + c4) = *(const float4*)(aC + (size_t)r*NAD + c4);
    }
  }

  float v[32][4];
  // ---- attention: AL = gbn(a @ w_att^T + b) ----
  gemm_gbn<NAD, DDIM>(smem, IN, w_att, b_att, gwa, gba, v);

  const float* priorC = prior + rowbase * DDIM;
  // z = AL * prior -> IN
  #pragma unroll
  for (int i = 0; i < 32; i++){
    int r = r0 + i;
    float4 pv = *(const float4*)(priorC + (size_t)r*DDIM + c0);
    *(float4*)(IN + r*DDIM + c0) =
        make_float4(v[i][0]*pv.x, v[i][1]*pv.y, v[i][2]*pv.z, v[i][3]*pv.w);
  }
  __syncthreads();

  // ---- sparsemax closed form: per-row max/sum/min -> tau ----
  {
    int wid = tid >> 5, lane = tid & 31;
    #pragma unroll 1
    for (int rr = 0; rr < 16; rr++){
      int r = wid*16 + rr;
      float sm_ = 0.0f, mx = -3.402823466e38f, mn = 3.402823466e38f;
      #pragma unroll
      for (int jj = 0; jj < 8; jj++){
        float zv = IN[r*DDIM + lane + jj*32];
        sm_ += zv; mx = fmaxf(mx, zv); mn = fminf(mn, zv);
      }
      #pragma unroll
      for (int off = 16; off > 0; off >>= 1){
        sm_ += __shfl_xor_sync(0xffffffffu, sm_, off);
        mx   = fmaxf(mx, __shfl_xor_sync(0xffffffffu, mx, off));
        mn   = fminf(mn, __shfl_xor_sync(0xffffffffu, mn, off));
      }
      if (lane == 0){
        // kz = 255 iff 1 + 255*max - sum > 0 (condition is monotone in rank)
        float tau;
        if (1.0f + 255.0f*mx - sm_ > 0.0f) tau = (sm_ + 1.0f) * (1.0f/255.0f);
        else                               tau = (mn + 1.0f) / 0.0f;
        TAU[r] = tau;
      }
    }
  }
  __syncthreads();

  // ---- m, new_prior outputs; X1 = x*m -> IN ----
  {
    const float* xC  = x   + rowbase * DDIM;
    float* outM = out + (size_t)N_TOT*384 + rowbase*DDIM;
    float* outP = out + (size_t)N_TOT*128 + rowbase*DDIM;
    #pragma unroll
    for (int i = 0; i < 32; i++){
      int r = r0 + i;
      float tau = TAU[r];
      float4 zv = *(const float4*)(IN + r*DDIM + c0);
      float4 pv = *(const float4*)(priorC + (size_t)r*DDIM + c0);
      float4 xv = *(const float4*)(xC + (size_t)r*DDIM + c0);
      float m0 = fmaxf(zv.x - tau, 0.0f);
      float m1 = fmaxf(zv.y - tau, 0.0f);
      float m2 = fmaxf(zv.z - tau, 0.0f);
      float m3 = fmaxf(zv.w - tau, 0.0f);
      *(float4*)(outM + (size_t)r*DDIM + c0) = make_float4(m0, m1, m2, m3);
      *(float4*)(outP + (size_t)r*DDIM + c0) =
          make_float4(pv.x*(GAMMA_F-m0), pv.y*(GAMMA_F-m1),
                      pv.z*(GAMMA_F-m2), pv.w*(GAMMA_F-m3));
      *(float4*)(IN + r*DDIM + c0) =
          make_float4(xv.x*m0, xv.y*m1, xv.z*m2, xv.w*m3);
    }
  }

  // ---- s1: G = gbn(X1 @ w_s1^T + b); h = GLU(G) -> HB ----
  gemm_gbn<DDIM, DDIM>(smem, IN, w_s1, b_s1, gw1, gb1, v);
  #pragma unroll
  for (int i = 0; i < 32; i++)
    *(float4*)(IN + (r0+i)*DDIM + c0) = make_float4(v[i][0], v[i][1], v[i][2], v[i][3]);
  __syncthreads();
  {
    int hc = (tid & 63) * 2;
    #pragma unroll
    for (int i = 0; i < 32; i++){
      int r = r0 + i;
      float2 u = *(const float2*)(IN + r*DDIM + hc);
      float2 g = *(const float2*)(IN + r*DDIM + HDIM + hc);
      *(float2*)(HB + r*HDIM + hc) = make_float2(u.x*sigmf(g.x), u.y*sigmf(g.y));
    }
  }

  const float S05 = 0.70710678118654752440f;

  // ---- three residual GLU blocks: h = s05*(h + GLU(gbn(h@W^T + b))) ----
  const float* Ws[3]  = {w_s2, w_d1, w_d2};
  const float* Bs[3]  = {b_s2, b_d1, b_d2};
  const float* GWs[3] = {gw2, gw3, gw4};
  const float* GBs[3] = {gb2, gb3, gb4};
  #pragma unroll 1
  for (int layer = 0; layer < 3; layer++){
    gemm_gbn<HDIM, HDIM>(smem, HB, Ws[layer], Bs[layer], GWs[layer], GBs[layer], v);
    #pragma unroll
    for (int i = 0; i < 32; i++)
      *(float4*)(IN + (r0+i)*DDIM + c0) = make_float4(v[i][0], v[i][1], v[i][2], v[i][3]);
    __syncthreads();
    {
      int hc = (tid & 63) * 2;
      #pragma unroll
      for (int i = 0; i < 32; i++){
        int r = r0 + i;
        float2 u  = *(const float2*)(IN + r*DDIM + hc);
        float2 g  = *(const float2*)(IN + r*DDIM + HDIM + hc);
        float2 ho = *(const float2*)(HB + r*HDIM + hc);
        *(float2*)(HB + r*HDIM + hc) =
            make_float2(S05*(ho.x + u.x*sigmf(g.x)),
                        S05*(ho.y + u.y*sigmf(g.y)));
      }
    }
    __syncthreads();
  }

  // ---- final outputs: a_out = h[:, :64], d = relu(h[:, 64:]) ----
  {
    int hc = (tid & 63) * 2;
    float* outA = out;
    float* outD = out + (size_t)N_TOT*64;
    #pragma unroll
    for (int i = 0; i < 32; i++){
      int r = r0 + i;
      size_t g = rowbase + r;
      float2 hv = *(const float2*)(HB + r*HDIM + hc);
      if (hc < 64){
        *(float2*)(outA + g*64 + hc) = hv;
      } else {
        *(float2*)(outD + g*64 + (hc - 64)) =
            make_float2(fmaxf(hv.x, 0.0f), fmaxf(hv.y, 0.0f));
      }
    }
  }
}

extern "C" void kernel_launch(void* const* d_in, const int* in_sizes, int n_in,
                              void* d_out, int out_size)
{
  (void)in_sizes; (void)n_in; (void)out_size;
  const float* x     = (const float*)d_in[0];
  const float* a     = (const float*)d_in[1];
  const float* prior = (const float*)d_in[2];
  const float* w_att = (const float*)d_in[3];
  const float* b_att = (const float*)d_in[4];
  const float* gwa   = (const float*)d_in[5];
  const float* gba   = (const float*)d_in[6];
  const float* w_s1  = (const float*)d_in[7];
  const float* b_s1  = (const float*)d_in[8];
  const float* gw1   = (const float*)d_in[9];
  const float* gb1   = (const float*)d_in[10];
  const float* w_s2  = (const float*)d_in[11];
  const float* b_s2  = (const float*)d_in[12];
  const float* gw2   = (const float*)d_in[13];
  const float* gb2   = (const float*)d_in[14];
  const float* w_d1  = (const float*)d_in[15];
  const float* b_d1  = (const float*)d_in[16];
  const float* gw3   = (const float*)d_in[17];
  const float* gb3   = (const float*)d_in[18];
  const float* w_d2  = (const float*)d_in[19];
  const float* b_d2  = (const float*)d_in[20];
  const float* gw4   = (const float*)d_in[21];
  const float* gb4   = (const float*)d_in[22];

  cudaFuncSetAttribute(tabnet_kernel,
                       cudaFuncAttributeMaxDynamicSharedMemorySize, SMEM_BYTES);
  tabnet_kernel<<<NCHUNK, 256, SMEM_BYTES>>>(
      x, a, prior,
      w_att, b_att, gwa, gba,
      w_s1, b_s1, gw1, gb1,
      w_s2, b_s2, gw2, gb2,
      w_d1, b_d1, gw3, gb3,
      w_d2, b_d2, gw4, gb4,
      (float*)d_out);
}

// round 10
// speedup vs baseline: 1.4787x; 1.4787x over previous
#include <cuda_runtime.h>
#include <cuda_bf16.h>

#define N_TOT 65536
#define VBS 128
#define NCHUNK 512
#define EPS_F 1e-5f
#define GAMMA_F 1.5f
#define S05C 0.70710678118654752440f

typedef unsigned int u32;

// smem layout (bytes)
#define OFF_A   0        // 8 x 16KB bf16 SW128 A tiles (hi 0..3, lo 4..7)
#define OFF_B   131072   // W hi chunk 32KB
#define OFF_BL  163840   // W lo chunk 32KB
#define OFF_SG  131072   // 128x128 fp32 sigmoid staging (aliases W)
#define OFF_PS  196608   // 4x256 fp32
#define OFF_PQ  200704   // 4x256 fp32
#define OFF_CA  204800   // 256 fp32
#define OFF_CB  205824   // 256 fp32
#define OFF_REX 206848   // 2x3x128 fp32
#define OFF_TAU 209920   // 128 fp32
#define SMEM_TOTAL 210432

__device__ __align__(16) __nv_bfloat16 g_wh[11*16384];
__device__ __align__(16) __nv_bfloat16 g_wl[11*16384];

__device__ __forceinline__ u32 swz(u32 o){ return o ^ ((o >> 3) & 0x70u); }
__device__ __forceinline__ u32 smem_u32(const void* p){
  u32 a; asm("{ .reg .u64 t; cvta.to.shared.u64 t, %1; cvt.u32.u64 %0, t; }"
             : "=r"(a) : "l"(p)); return a;
}
__device__ __forceinline__ float sigf(float x){
  return __fdividef(1.0f, 1.0f + __expf(-x));
}
__device__ __forceinline__ void split2(float a, float b, u32& hp, u32& lp){
  __nv_bfloat16 ha=__float2bfloat16(a), hb=__float2bfloat16(b);
  __nv_bfloat16 la=__float2bfloat16(a-__bfloat162float(ha));
  __nv_bfloat16 lb=__float2bfloat16(b-__bfloat162float(hb));
  hp = ((u32)__bfloat16_as_ushort(hb)<<16) | __bfloat16_as_ushort(ha);
  lp = ((u32)__bfloat16_as_ushort(lb)<<16) | __bfloat16_as_ushort(la);
}
__device__ __forceinline__ float bflo(u32 v){
  return __bfloat162float(__ushort_as_bfloat16((unsigned short)(v&0xffffu)));
}
__device__ __forceinline__ float bfhi(u32 v){
  return __bfloat162float(__ushort_as_bfloat16((unsigned short)(v>>16)));
}

#define LDSM4(r, a) \
  asm volatile("ldmatrix.sync.aligned.m8n8.x4.shared.b16 {%0,%1,%2,%3}, [%4];" \
    : "=r"((r)[0]),"=r"((r)[1]),"=r"((r)[2]),"=r"((r)[3]) : "r"(a))

#define MMA(d, a, b0, b1) \
  asm volatile("mma.sync.aligned.m16n8k16.row.col.f32.bf16.bf16.f32 " \
    "{%0,%1,%2,%3},{%4,%5,%6,%7},{%8,%9},{%0,%1,%2,%3};" \
    : "+f"((d)[0]),"+f"((d)[1]),"+f"((d)[2]),"+f"((d)[3]) \
    : "r"((a)[0]),"r"((a)[1]),"r"((a)[2]),"r"((a)[3]),"r"(b0),"r"(b1))

// ---- prep: fp32 weights -> bf16 hi/lo in SW128 image order ----
__global__ void prep_weights(const float* __restrict__ w_att,
                             const float* __restrict__ w_s1,
                             const float* __restrict__ w_s2,
                             const float* __restrict__ w_d1,
                             const float* __restrict__ w_d2){
  int t = blockIdx.x; const float* W; int K, kc;
  if (t == 0)     { W = w_att; K = 64;  kc = 0;   }
  else if (t < 5) { W = w_s1;  K = 256; kc = t-1; }
  else if (t < 7) { W = w_s2;  K = 128; kc = t-5; }
  else if (t < 9) { W = w_d1;  K = 128; kc = t-7; }
  else            { W = w_d2;  K = 128; kc = t-9; }
  for (int idx = threadIdx.x; idx < 16384; idx += 256){
    int n = idx >> 6, k = idx & 63;
    float w = W[n*K + kc*64 + k];
    __nv_bfloat16 hi = __float2bfloat16(w);
    __nv_bfloat16 lo = __float2bfloat16(w - __bfloat162float(hi));
    u32 off = swz((u32)(n*128 + k*2)) >> 1;
    g_wh[t*16384 + off] = hi;
    g_wl[t*16384 + off] = lo;
  }
}

// GEMM: C[128x256] += A[128xK] * W^T, K = NC*64, 3-term bf16 split.
template<int NC>
__device__ __forceinline__ void run_gemm(char* smem, u32 smb,
    float (&acc)[2][16][4], int wbase, int rg, int ch, int lane){
  const int tid = threadIdx.x;
  #pragma unroll
  for (int mi=0;mi<2;mi++)
    #pragma unroll
    for (int nt=0;nt<16;nt++)
      #pragma unroll
      for (int j=0;j<4;j++) acc[mi][nt][j]=0.0f;
  const int arow = rg*32 + (lane&15);
  const int brow = ch*128 + (lane&15);
  const int half = (lane>>4)*16;
  #pragma unroll 1
  for (int c=0;c<NC;c++){
    __syncthreads();
    const float4* sH=(const float4*)(g_wh+(wbase+c)*16384);
    const float4* sL=(const float4*)(g_wl+(wbase+c)*16384);
    float4* dH=(float4*)(smem+OFF_B);
    float4* dL=(float4*)(smem+OFF_BL);
    #pragma unroll
    for (int i=0;i<8;i++) dH[tid+256*i]=sH[tid+256*i];
    #pragma unroll
    for (int i=0;i<8;i++) dL[tid+256*i]=sL[tid+256*i];
    __syncthreads();
    #pragma unroll
    for (int k=0;k<4;k++){
      u32 AH[2][4], AL[2][4];
      #pragma unroll
      for (int mi=0;mi<2;mi++){
        u32 o = swz((u32)((arow+mi*16)*128 + k*32 + half));
        LDSM4(AH[mi], smb + OFF_A + c*16384 + o);
        LDSM4(AL[mi], smb + OFF_A + (4+c)*16384 + o);
      }
      #pragma unroll
      for (int nt=0;nt<8;nt++){
        u32 BH[4], BL[4];
        u32 o = swz((u32)((brow+nt*16)*128 + k*32 + half));
        LDSM4(BH, smb + OFF_B + o);
        LDSM4(BL, smb + OFF_BL + o);
        #pragma unroll
        for (int mi=0;mi<2;mi++){
          #pragma unroll
          for (int j=0;j<2;j++){
            MMA(acc[mi][nt*2+j], AH[mi], BH[j], BH[j+2]);
            MMA(acc[mi][nt*2+j], AL[mi], BH[j], BH[j+2]);
            MMA(acc[mi][nt*2+j], AH[mi], BL[j], BL[j+2]);
          }
        }
      }
    }
  }
}

// ghost batch norm over the 128-row chunk (biases cancel; dropped upstream)
__device__ __forceinline__ void epi_gbn(char* smem, float (&acc)[2][16][4],
    const float* __restrict__ gw, const float* __restrict__ gb,
    int rg, int ch, int lane){
  float* PS=(float*)(smem+OFF_PS);
  float* PQ=(float*)(smem+OFF_PQ);
  #pragma unroll
  for (int nt=0;nt<16;nt++){
    float s0=0,s1=0,q0=0,q1=0;
    #pragma unroll
    for (int mi=0;mi<2;mi++){
      s0+=acc[mi][nt][0]+acc[mi][nt][2];
      s1+=acc[mi][nt][1]+acc[mi][nt][3];
      q0+=acc[mi][nt][0]*acc[mi][nt][0]+acc[mi][nt][2]*acc[mi][nt][2];
      q1+=acc[mi][nt][1]*acc[mi][nt][1]+acc[mi][nt][3]*acc[mi][nt][3];
    }
    #pragma unroll
    for (int off=4;off<32;off<<=1){
      s0+=__shfl_xor_sync(~0u,s0,off); s1+=__shfl_xor_sync(~0u,s1,off);
      q0+=__shfl_xor_sync(~0u,q0,off); q1+=__shfl_xor_sync(~0u,q1,off);
    }
    if (lane<4){
      int cc = ch*128 + nt*8 + lane*2;
      PS[rg*256+cc]=s0; PS[rg*256+cc+1]=s1;
      PQ[rg*256+cc]=q0; PQ[rg*256+cc+1]=q1;
    }
  }
  __syncthreads();
  {
    int cc=threadIdx.x;
    float sum=PS[cc]+PS[256+cc]+PS[512+cc]+PS[768+cc];
    float sq =PQ[cc]+PQ[256+cc]+PQ[512+cc]+PQ[768+cc];
    float mean=sum*(1.0f/128.0f);
    float var = sq*(1.0f/128.0f)-mean*mean;
    float A=rsqrtf(var+EPS_F)*gw[cc];
    ((float*)(smem+OFF_CA))[cc]=A;
    ((float*)(smem+OFF_CB))[cc]=gb[cc]-mean*A;
  }
  __syncthreads();
  const float* CA=(const float*)(smem+OFF_CA);
  const float* CB=(const float*)(smem+OFF_CB);
  #pragma unroll
  for (int nt=0;nt<16;nt++){
    int cc=ch*128+nt*8+(lane&3)*2;
    float a0=CA[cc],a1=CA[cc+1],b0=CB[cc],b1=CB[cc+1];
    #pragma unroll
    for (int mi=0;mi<2;mi++){
      acc[mi][nt][0]=acc[mi][nt][0]*a0+b0;
      acc[mi][nt][1]=acc[mi][nt][1]*a1+b1;
      acc[mi][nt][2]=acc[mi][nt][2]*a0+b0;
      acc[mi][nt][3]=acc[mi][nt][3]*a1+b1;
    }
  }
}

// GLU + (optional residual) + store h as bf16 tiles or final outputs
__device__ __forceinline__ void glu_tail(char* smem, float (&acc)[2][16][4],
    int rg, int ch, int lane, size_t rowbase, float* out, int res, int fin){
  float* SG=(float*)(smem+OFF_SG);
  if (ch==1){
    #pragma unroll
    for (int nt=0;nt<16;nt++){
      int c=nt*8+(lane&3)*2;
      #pragma unroll
      for (int s=0;s<4;s++){
        int r=rg*32+(lane>>2)+s*8;
        float* A0=&acc[s>>1][nt][(s&1)*2];
        SG[r*128+c]=sigf(A0[0]); SG[r*128+c+1]=sigf(A0[1]);
      }
    }
  }
  __syncthreads();
  if (ch==0){
    #pragma unroll
    for (int nt=0;nt<16;nt++){
      int c=nt*8+(lane&3)*2;
      #pragma unroll
      for (int s=0;s<4;s++){
        int r=rg*32+(lane>>2)+s*8;
        float* A0=&acc[s>>1][nt][(s&1)*2];
        float h0=A0[0]*SG[r*128+c], h1=A0[1]*SG[r*128+c+1];
        int chk=c>>6;
        u32 off=swz((u32)(r*128+(c&63)*2));
        u32* tH=(u32*)(smem+OFF_A+chk*16384+off);
        u32* tL=(u32*)(smem+OFF_A+(4+chk)*16384+off);
        if (res){
          u32 hp=*tH, lp=*tL;
          h0=S05C*((bflo(hp)+bflo(lp))+h0);
          h1=S05C*((bfhi(hp)+bfhi(lp))+h1);
        }
        if (fin){
          if (c<64) *(float2*)(out+(rowbase+r)*64+c)=make_float2(h0,h1);
          else *(float2*)(out+(size_t)N_TOT*64+(rowbase+r)*64+(c-64))=
                 make_float2(fmaxf(h0,0.0f),fmaxf(h1,0.0f));
        } else {
          u32 hp,lp; split2(h0,h1,hp,lp);
          *tH=hp; *tL=lp;
        }
      }
    }
  }
}

__global__ void __launch_bounds__(256,1)
tabnet_mma(const float* __restrict__ x, const float* __restrict__ a,
           const float* __restrict__ prior,
           const float* __restrict__ gwa, const float* __restrict__ gba,
           const float* __restrict__ gw1, const float* __restrict__ gb1,
           const float* __restrict__ gw2, const float* __restrict__ gb2,
           const float* __restrict__ gw3, const float* __restrict__ gb3,
           const float* __restrict__ gw4, const float* __restrict__ gb4,
           float* __restrict__ out){
  extern __shared__ char smem[];
  const int tid=threadIdx.x, warp=tid>>5, lane=tid&31;
  const int rg=warp&3, ch=warp>>2;
  const u32 smb=smem_u32(smem);
  const size_t rowbase=(size_t)blockIdx.x*VBS;

  // stage `a` (128x64) -> A tile 0 (hi) / 4 (lo)
  for (int idx=tid; idx<128*32; idx+=256){
    int r=idx>>5, p=idx&31;
    float2 v=*(const float2*)(a+(rowbase+r)*64+p*2);
    u32 hp,lp; split2(v.x,v.y,hp,lp);
    u32 off=swz((u32)(r*128+p*4));
    *(u32*)(smem+OFF_A+off)=hp;
    *(u32*)(smem+OFF_A+4*16384+off)=lp;
  }

  float acc[2][16][4];
  // ---- attention GEMM + GBN ----
  run_gemm<1>(smem,smb,acc,0,rg,ch,lane);
  epi_gbn(smem,acc,gwa,gba,rg,ch,lane);

  // z = gbn * prior; per-row sum/max/min for closed-form sparsemax
  const float* priorB = prior + rowbase*256;
  float rs[4]={0,0,0,0};
  float rmx[4]={-3.4e38f,-3.4e38f,-3.4e38f,-3.4e38f};
  float rmn[4]={3.4e38f,3.4e38f,3.4e38f,3.4e38f};
  #pragma unroll
  for (int nt=0;nt<16;nt++){
    int c=ch*128+nt*8+(lane&3)*2;
    #pragma unroll
    for (int s=0;s<4;s++){
      int r=rg*32+(lane>>2)+s*8;
      float2 pv=*(const float2*)(priorB+r*256+c);
      float* A0=&acc[s>>1][nt][(s&1)*2];
      A0[0]*=pv.x; A0[1]*=pv.y;
      rs[s]+=A0[0]+A0[1];
      rmx[s]=fmaxf(rmx[s],fmaxf(A0[0],A0[1]));
      rmn[s]=fminf(rmn[s],fminf(A0[0],A0[1]));
    }
  }
  #pragma unroll
  for (int off=1;off<4;off<<=1){
    #pragma unroll
    for (int s=0;s<4;s++){
      rs[s]+=__shfl_xor_sync(~0u,rs[s],off);
      rmx[s]=fmaxf(rmx[s],__shfl_xor_sync(~0u,rmx[s],off));
      rmn[s]=fminf(rmn[s],__shfl_xor_sync(~0u,rmn[s],off));
    }
  }
  float* REX=(float*)(smem+OFF_REX);
  float* TAU=(float*)(smem+OFF_TAU);
  if ((lane&3)==0){
    #pragma unroll
    for (int s=0;s<4;s++){
      int r=rg*32+(lane>>2)+s*8;
      REX[ch*384+r]=rs[s]; REX[ch*384+128+r]=rmx[s]; REX[ch*384+256+r]=rmn[s];
    }
  }
  __syncthreads();
  if (tid<128){
    float S=REX[tid]+REX[384+tid];
    float MX=fmaxf(REX[128+tid],REX[384+128+tid]);
    float MN=fminf(REX[256+tid],REX[384+256+tid]);
    // kz = 255 iff 1 + 255*max - sum > 0 (condition monotone in rank)
    TAU[tid]=(1.0f+255.0f*MX-S>0.0f) ? (S+1.0f)*(1.0f/255.0f) : (MN+1.0f)/0.0f;
  }
  __syncthreads();

  // m, new_prior outputs; X1 = x*m -> A tiles 0..3 / 4..7
  {
    const float* xB = x + rowbase*256;
    float* outM = out + (size_t)N_TOT*384 + rowbase*256;
    float* outP = out + (size_t)N_TOT*128 + rowbase*256;
    #pragma unroll
    for (int nt=0;nt<16;nt++){
      int c=ch*128+nt*8+(lane&3)*2;
      #pragma unroll
      for (int s=0;s<4;s++){
        int r=rg*32+(lane>>2)+s*8;
        float tau=TAU[r];
        float* A0=&acc[s>>1][nt][(s&1)*2];
        float m0=fmaxf(A0[0]-tau,0.0f), m1=fmaxf(A0[1]-tau,0.0f);
        *(float2*)(outM+r*256+c)=make_float2(m0,m1);
        float2 pv=*(const float2*)(priorB+r*256+c);
        *(float2*)(outP+r*256+c)=make_float2(pv.x*(GAMMA_F-m0),pv.y*(GAMMA_F-m1));
        float2 xv=*(const float2*)(xB+r*256+c);
        u32 hp,lp; split2(xv.x*m0,xv.y*m1,hp,lp);
        int chk=c>>6;
        u32 off=swz((u32)(r*128+(c&63)*2));
        *(u32*)(smem+OFF_A+chk*16384+off)=hp;
        *(u32*)(smem+OFF_A+(4+chk)*16384+off)=lp;
      }
    }
  }

  // ---- s1 GEMM (K=256) + GBN + GLU -> h tiles 0,1 / 4,5 ----
  run_gemm<4>(smem,smb,acc,1,rg,ch,lane);
  epi_gbn(smem,acc,gw1,gb1,rg,ch,lane);
  glu_tail(smem,acc,rg,ch,lane,rowbase,out,0,0);

  // ---- three residual GLU layers (K=128) ----
  const float* GW[3]={gw2,gw3,gw4};
  const float* GB[3]={gb2,gb3,gb4};
  #pragma unroll 1
  for (int L=0;L<3;L++){
    run_gemm<2>(smem,smb,acc,5+2*L,rg,ch,lane);
    epi_gbn(smem,acc,GW[L],GB[L],rg,ch,lane);
    glu_tail(smem,acc,rg,ch,lane,rowbase,out,1,(L==2)?1:0);
  }
}

extern "C" void kernel_launch(void* const* d_in, const int* in_sizes, int n_in,
                              void* d_out, int out_size){
  (void)in_sizes; (void)n_in; (void)out_size;
  const float* x     = (const float*)d_in[0];
  const float* a     = (const float*)d_in[1];
  const float* prior = (const float*)d_in[2];
  const float* w_att = (const float*)d_in[3];
  const float* gwa   = (const float*)d_in[5];
  const float* gba   = (const float*)d_in[6];
  const float* w_s1  = (const float*)d_in[7];
  const float* gw1   = (const float*)d_in[9];
  const float* gb1   = (const float*)d_in[10];
  const float* w_s2  = (const float*)d_in[11];
  const float* gw2   = (const float*)d_in[13];
  const float* gb2   = (const float*)d_in[14];
  const float* w_d1  = (const float*)d_in[15];
  const float* gw3   = (const float*)d_in[17];
  const float* gb3   = (const float*)d_in[18];
  const float* w_d2  = (const float*)d_in[19];
  const float* gw4   = (const float*)d_in[21];
  const float* gb4   = (const float*)d_in[22];

  prep_weights<<<11, 256>>>(w_att, w_s1, w_s2, w_d1, w_d2);
  cudaFuncSetAttribute(tabnet_mma,
      cudaFuncAttributeMaxDynamicSharedMemorySize, SMEM_TOTAL);
  tabnet_mma<<<NCHUNK, 256, SMEM_TOTAL>>>(
      x, a, prior, gwa, gba, gw1, gb1, gw2, gb2, gw3, gb3, gw4, gb4,
      (float*)d_out);
}